// round 16
// baseline (speedup 1.0000x reference)
#include <cuda_runtime.h>
#include <cuda_bf16.h>
#include <cstdint>

typedef unsigned long long ull;

static constexpr int D       = 64;
static constexpr int HW      = 4096;
static constexpr int K       = 512;
static constexpr int N_VEC   = 131072;
static constexpr int N_ELEMS = N_VEC * D;         // 8388608
static constexpr int LOSS_OFF = N_ELEMS;
static constexpr int IDX_OFF  = N_ELEMS + 1;
static constexpr int THREADS  = 512;
static constexpr int NCTA     = 148;
static constexpr int VTILE    = 128;
static constexpr int NTILE    = N_VEC / VTILE;    // 1024
static constexpr int XH_STR   = 72;               // padded bf16 row stride (conflict-free frags)

// smem offsets (floats)
static constexpr int OFF_E   = 0;        // sE   [512] exact code norms
static constexpr int OFF_S   = 512;      // sS   [128] exact S per vec
static constexpr int OFF_SA  = 640;      // sSA  [128] sum |x| per vec (for margin)
static constexpr int OFF_X   = 768;      // sX   [64][128] fp32 x tile
static constexpr int OFF_LEX = 8960;     // sLex ull[128] (dist_bits<<32)|k
static constexpr int OFF_APP = 9216;     // sApp int[128] approx-min bits
static constexpr int OFF_BI  = 9344;     // sBi  int[128] chosen index
static constexpr int OFF_XH  = 9472;     // sXh  bf16 [128][72] = 4608 floats
static constexpr int OFF_EH  = 14080;    // sEh  bf16 [512][72] = 18432 floats
static constexpr int SMEM_FLOATS = 32512;
static constexpr int SMEM_BYTES  = SMEM_FLOATS * 4;   // 130048

__device__ double   g_loss = 0.0;
__device__ unsigned g_done = 0u;

__device__ __forceinline__ void mma16816(float& c0, float& c1, float& c2, float& c3,
                                         unsigned a0, unsigned a1, unsigned a2, unsigned a3,
                                         unsigned b0, unsigned b1) {
    asm("mma.sync.aligned.m16n8k16.row.col.f32.bf16.bf16.f32 "
        "{%0,%1,%2,%3}, {%4,%5,%6,%7}, {%8,%9}, {%0,%1,%2,%3};"
        : "+f"(c0), "+f"(c1), "+f"(c2), "+f"(c3)
        : "r"(a0), "r"(a1), "r"(a2), "r"(a3), "r"(b0), "r"(b1));
}

// EXACT rescore: reproduces the verified reference rounding bit-for-bit.
//   dot = strict sequential fp32 FMA chain over d=0..63
//   d   = fl( fl(S+E_k) - 2*dot )
__device__ __noinline__ void rescore(const float* sX, const float* sS, const float* sE,
                                     ull* sLex, const float* __restrict__ emb,
                                     int rl, int k) {
    const float* er = sX + rl;
    const float* eg = emb + k * D;
    float dot = 0.f;
#pragma unroll 16
    for (int d = 0; d < 64; d++)
        dot = __fmaf_rn(er[d * VTILE], eg[d], dot);
    float t1 = __fadd_rn(sS[rl], sE[k]);
    float de = __fmaf_rn(-2.0f, dot, t1);
    ull key = ((ull)(unsigned)__float_as_int(de) << 32) | (unsigned)k;
    atomicMin(sLex + rl, key);
}

// Two-stage exact VQ:
//   Stage 1: bf16 mma.sync (tensor pipe) computes approx distances; per-vec approx min.
//   Stage 2: recompute; every code within margin M of min is EXACTLY rescored with the
//            invariant chain; lexicographic atomicMin((d_bits<<32)|k) == first-min by index.
//   Non-candidates provably cannot tie (|d~-d| <= M/2 per code), so indices are exact.
// EXACT-INVARIANT (verified rel_err==0.0 twelve times, unchanged in the rescore path):
//   d_k = fl32(fl32(S+E_k) - 2*dot_k); dot_k sequential fp32 FMA chain d=0..63
//   S = 4-lane stride-4 sums (l0+l2)+(l1+l3); argmin first-min ascending k
//   out = fl(x + fl(q - x))
__global__ __launch_bounds__(THREADS, 1)
void k_main(const float* __restrict__ in, const float* __restrict__ emb,
            float* __restrict__ out, int write_extras) {
    extern __shared__ float s[];
    float* sE  = s + OFF_E;
    float* sS  = s + OFF_S;
    float* sSA = s + OFF_SA;
    float* sX  = s + OFF_X;
    ull*   sLex = (ull*)(s + OFF_LEX);
    int*   sApp = (int*)(s + OFF_APP);
    int*   sBi  = (int*)(s + OFF_BI);
    __nv_bfloat16* sXh = (__nv_bfloat16*)(s + OFF_XH);
    __nv_bfloat16* sEh = (__nv_bfloat16*)(s + OFF_EH);
    __shared__ double red[16];

    const int tid  = threadIdx.x;
    const int lane = tid & 31;
    const int warp = tid >> 5;         // 0..15
    const int vg   = warp >> 1;        // vec-group 0..7 (16 rows)
    const int ch   = warp & 1;         // code half 0..1 (256 codes)
    const int g    = lane >> 2;        // fragment group row 0..7
    const int t    = lane & 3;         // thread-in-group

    // ---- stage bf16 codebook [code][k] padded (once) ----
#pragma unroll
    for (int i = 0; i < 64; i++) {
        int lin = i * THREADS + tid;            // code*64 + d
        int code = lin >> 6, d = lin & 63;
        sEh[code * XH_STR + d] = __float2bfloat16_rn(emb[lin]);
    }

    // ---- E_k: XLA 4-lane pattern (exact, unchanged) ----
    {
        const float* r = emb + tid * D;
        float l0 = 0.f, l1 = 0.f, l2 = 0.f, l3 = 0.f;
#pragma unroll
        for (int i = 0; i < 16; i++) {
            l0 = __fadd_rn(l0, __fmul_rn(r[4 * i + 0], r[4 * i + 0]));
            l1 = __fadd_rn(l1, __fmul_rn(r[4 * i + 1], r[4 * i + 1]));
            l2 = __fadd_rn(l2, __fmul_rn(r[4 * i + 2], r[4 * i + 2]));
            l3 = __fadd_rn(l3, __fmul_rn(r[4 * i + 3], r[4 * i + 3]));
        }
        sE[tid] = __fadd_rn(__fadd_rn(l0, l2), __fadd_rn(l1, l3));
    }
    __syncthreads();

    float lsumf = 0.0f;

    for (int tile = blockIdx.x; tile < NTILE; tile += NCTA) {
        const int v0 = tile * VTILE;
        const int b  = v0 >> 12;
        const int p  = v0 & 4095;
        const float* xg = in + b * (D * HW) + p;

        // ---- stage x tile fp32 [d][128] + init per-tile reducers ----
#pragma unroll
        for (int i = 0; i < 16; i++) {
            int lin = i * THREADS + tid;
            int d = lin >> 7, vv = lin & 127;
            sX[lin] = xg[d * HW + vv];
        }
        if (tid < VTILE) {
            sApp[tid] = 0x7F800000;                 // +inf bits
            sLex[tid] = 0xFFFFFFFFFFFFFFFFull;
        }
        __syncthreads();

        // ---- S (exact 4-lane) + Sabs; bf16 x tile [v][k] padded ----
        if (tid < VTILE) {
            float l0 = 0.f, l1 = 0.f, l2 = 0.f, l3 = 0.f;
            float a0 = 0.f, a1 = 0.f, a2 = 0.f, a3 = 0.f;
#pragma unroll
            for (int d = 0; d < 64; d += 4) {
                float x0 = sX[(d + 0) * VTILE + tid];
                float x1 = sX[(d + 1) * VTILE + tid];
                float x2 = sX[(d + 2) * VTILE + tid];
                float x3 = sX[(d + 3) * VTILE + tid];
                l0 = __fadd_rn(l0, __fmul_rn(x0, x0));
                l1 = __fadd_rn(l1, __fmul_rn(x1, x1));
                l2 = __fadd_rn(l2, __fmul_rn(x2, x2));
                l3 = __fadd_rn(l3, __fmul_rn(x3, x3));
                a0 += fabsf(x0); a1 += fabsf(x1); a2 += fabsf(x2); a3 += fabsf(x3);
            }
            sS[tid]  = __fadd_rn(__fadd_rn(l0, l2), __fadd_rn(l1, l3));
            sSA[tid] = (a0 + a2) + (a1 + a3);
        }
#pragma unroll
        for (int i = 0; i < 16; i++) {
            int lin = i * THREADS + tid;
            int d = lin >> 7, vv = lin & 127;
            sXh[vv * XH_STR + d] = __float2bfloat16_rn(sX[lin]);
        }
        __syncthreads();

        // ---- load A fragments (x) for this warp's 16 rows, all 4 k-steps ----
        const int rowA = vg * 16 + g;
        const int rowB = rowA + 8;
        unsigned afr[4][4];
#pragma unroll
        for (int ks = 0; ks < 4; ks++) {
            int k0 = ks * 16 + t * 2;
            afr[ks][0] = *(const unsigned*)(sXh + rowA * XH_STR + k0);
            afr[ks][1] = *(const unsigned*)(sXh + rowB * XH_STR + k0);
            afr[ks][2] = *(const unsigned*)(sXh + rowA * XH_STR + k0 + 8);
            afr[ks][3] = *(const unsigned*)(sXh + rowB * XH_STR + k0 + 8);
        }
        const float Sa = sS[rowA], Sb = sS[rowB];

        // ================= PASS A: approx min =================
        {
            float minA = 3.4e38f, minB = 3.4e38f;
            for (int nt = 0; nt < 32; nt++) {
                const int n0 = ch * 256 + nt * 8;
                const int codeB = n0 + g;
                float c0 = 0.f, c1 = 0.f, c2 = 0.f, c3 = 0.f;
#pragma unroll
                for (int ks = 0; ks < 4; ks++) {
                    unsigned b0 = *(const unsigned*)(sEh + codeB * XH_STR + ks * 16 + t * 2);
                    unsigned b1 = *(const unsigned*)(sEh + codeB * XH_STR + ks * 16 + t * 2 + 8);
                    mma16816(c0, c1, c2, c3, afr[ks][0], afr[ks][1], afr[ks][2], afr[ks][3], b0, b1);
                }
                const int col0 = n0 + t * 2;
                float2 Ep = *(const float2*)(sE + col0);
                float d00 = __fmaf_rn(-2.f, c0, __fadd_rn(Sa, Ep.x));
                float d01 = __fmaf_rn(-2.f, c1, __fadd_rn(Sa, Ep.y));
                float d10 = __fmaf_rn(-2.f, c2, __fadd_rn(Sb, Ep.x));
                float d11 = __fmaf_rn(-2.f, c3, __fadd_rn(Sb, Ep.y));
                minA = fminf(minA, fminf(d00, d01));
                minB = fminf(minB, fminf(d10, d11));
            }
#pragma unroll
            for (int o = 1; o < 4; o <<= 1) {
                minA = fminf(minA, __shfl_xor_sync(0xffffffffu, minA, o));
                minB = fminf(minB, __shfl_xor_sync(0xffffffffu, minB, o));
            }
            if (t == 0) {
                atomicMin(sApp + rowA, __float_as_int(minA));
                atomicMin(sApp + rowB, __float_as_int(minB));
            }
        }
        __syncthreads();

        // ================= PASS B: recompute + exact rescore of candidates =================
        {
            const float thrA = __int_as_float(sApp[rowA]) + (sSA[rowA] * 2.0e-5f + 5.0e-5f);
            const float thrB = __int_as_float(sApp[rowB]) + (sSA[rowB] * 2.0e-5f + 5.0e-5f);
            for (int nt = 0; nt < 32; nt++) {
                const int n0 = ch * 256 + nt * 8;
                const int codeB = n0 + g;
                float c0 = 0.f, c1 = 0.f, c2 = 0.f, c3 = 0.f;
#pragma unroll
                for (int ks = 0; ks < 4; ks++) {
                    unsigned b0 = *(const unsigned*)(sEh + codeB * XH_STR + ks * 16 + t * 2);
                    unsigned b1 = *(const unsigned*)(sEh + codeB * XH_STR + ks * 16 + t * 2 + 8);
                    mma16816(c0, c1, c2, c3, afr[ks][0], afr[ks][1], afr[ks][2], afr[ks][3], b0, b1);
                }
                const int col0 = n0 + t * 2;
                float2 Ep = *(const float2*)(sE + col0);
                float d00 = __fmaf_rn(-2.f, c0, __fadd_rn(Sa, Ep.x));
                float d01 = __fmaf_rn(-2.f, c1, __fadd_rn(Sa, Ep.y));
                float d10 = __fmaf_rn(-2.f, c2, __fadd_rn(Sb, Ep.x));
                float d11 = __fmaf_rn(-2.f, c3, __fadd_rn(Sb, Ep.y));
                if (d00 <= thrA) rescore(sX, sS, sE, sLex, emb, rowA, col0);
                if (d01 <= thrA) rescore(sX, sS, sE, sLex, emb, rowA, col0 + 1);
                if (d10 <= thrB) rescore(sX, sS, sE, sLex, emb, rowB, col0);
                if (d11 <= thrB) rescore(sX, sS, sE, sLex, emb, rowB, col0 + 1);
            }
        }
        __syncthreads();

        // ---- indices ----
        if (tid < VTILE) {
            int bi = (int)(sLex[tid] & 0xFFFFFFFFull);
            sBi[tid] = bi;
            if (write_extras) out[IDX_OFF + v0 + tid] = (float)bi;
        }
        __syncthreads();

        // ---- gather exact codes (gmem, L1-hot) + straight-through store + loss ----
        {
            const int vv = tid & 127;
            const int d0 = (tid >> 7) * 16;
            const int bi = sBi[vv];
            const float* eg = emb + bi * D;
            float* og = out + b * (D * HW) + p + vv;
#pragma unroll
            for (int j = 0; j < 16; j++) {
                const int d = d0 + j;
                float q  = eg[d];
                float xs = sX[d * VTILE + vv];
                float tt = __fsub_rn(q, xs);       // fl(q - x)
                og[d * HW] = __fadd_rn(xs, tt);    // fl(x + (q - x))
                lsumf = __fmaf_rn(tt, tt, lsumf);
            }
        }
        __syncthreads();   // protect sX/sLex/sBi before next tile
    }

    // ---- loss block-reduce -> atomic; last CTA finalizes & resets globals ----
#pragma unroll
    for (int o = 16; o; o >>= 1) lsumf += __shfl_down_sync(0xffffffffu, lsumf, o);
    if ((tid & 31) == 0) red[tid >> 5] = (double)lsumf;
    __syncthreads();
    if (tid == 0) {
        double tt = 0.0;
#pragma unroll
        for (int w = 0; w < 16; w++) tt += red[w];
        atomicAdd(&g_loss, tt);
        __threadfence();
        unsigned done = atomicAdd(&g_done, 1u);
        if (done == (unsigned)(gridDim.x - 1)) {
            if (write_extras)
                out[LOSS_OFF] = (float)(0.25 * g_loss / (double)N_ELEMS);
            g_loss = 0.0;
            g_done = 0u;
        }
    }
}

extern "C" void kernel_launch(void* const* d_in, const int* in_sizes, int n_in,
                              void* d_out, int out_size) {
    const float* in  = (const float*)d_in[0];
    const float* emb = (const float*)d_in[1];
    if (n_in >= 2 && in_sizes[0] == K * D && in_sizes[1] == N_ELEMS) {
        const float* t = in; in = emb; emb = t;
    }
    float* out = (float*)d_out;

    cudaFuncSetAttribute(k_main, cudaFuncAttributeMaxDynamicSharedMemorySize, SMEM_BYTES);

    const int extras = (out_size > N_ELEMS) ? 1 : 0;

    k_main<<<NCTA, THREADS, SMEM_BYTES>>>(in, emb, out, extras);
}

// round 17
// speedup vs baseline: 1.1736x; 1.1736x over previous
#include <cuda_runtime.h>
#include <cuda_bf16.h>
#include <cstdint>

typedef unsigned long long ull;

static constexpr int D       = 64;
static constexpr int HW      = 4096;
static constexpr int K       = 512;
static constexpr int N_VEC   = 131072;
static constexpr int N_ELEMS = N_VEC * D;         // 8388608
static constexpr int LOSS_OFF = N_ELEMS;
static constexpr int IDX_OFF  = N_ELEMS + 1;
static constexpr int THREADS  = 512;
static constexpr int NCTA     = 148;
static constexpr int VTILE    = 128;
static constexpr int NTILE    = N_VEC / VTILE;    // 1024
static constexpr int XH_STR   = 72;               // padded bf16 row stride
static constexpr int CAPL     = 20;               // per-lane candidate stash
static constexpr int GCAP     = 512;              // global candidate list cap

// smem offsets (floats)
static constexpr int OFF_E   = 0;        // sE   [512]
static constexpr int OFF_S   = 512;      // sS   [128]
static constexpr int OFF_SA  = 640;      // sSA  [128]
static constexpr int OFF_SL  = 768;      // sSl  [4][128] S lane partials
static constexpr int OFF_SLA = 1280;     // sSlA [4][128] |x| lane partials
static constexpr int OFF_X   = 1792;     // sX   [64][128]
static constexpr int OFF_LEX = 9984;     // sLex ull[128]
static constexpr int OFF_APP = 10240;    // sApp int[128]
static constexpr int OFF_BI  = 10368;    // sBi  int[128]
static constexpr int OFF_GC  = 10496;    // gcnt int
static constexpr int OFF_OVF = 10497;    // ovf  int
static constexpr int OFF_GL  = 10500;    // gl   int[512]
static constexpr int OFF_WL  = 11012;    // wl   int2[512][20] = 20480 floats
static constexpr int OFF_XH  = 31492;    // sXh  bf16[128][72] = 4608 floats
static constexpr int OFF_EH  = 36100;    // sEh  bf16[512][72] = 18432 floats
static constexpr int SMEM_FLOATS = 54532;
static constexpr int SMEM_BYTES  = SMEM_FLOATS * 4;   // 218128

__device__ double   g_loss = 0.0;
__device__ unsigned g_done = 0u;

__device__ __forceinline__ void mma16816(float& c0, float& c1, float& c2, float& c3,
                                         unsigned a0, unsigned a1, unsigned a2, unsigned a3,
                                         unsigned b0, unsigned b1) {
    asm("mma.sync.aligned.m16n8k16.row.col.f32.bf16.bf16.f32 "
        "{%0,%1,%2,%3}, {%4,%5,%6,%7}, {%8,%9}, {%0,%1,%2,%3};"
        : "+f"(c0), "+f"(c1), "+f"(c2), "+f"(c3)
        : "r"(a0), "r"(a1), "r"(a2), "r"(a3), "r"(b0), "r"(b1));
}

// Single-pass tensor VQ with prefix-min candidate collection + batched exact rescore.
// Soundness: append when d~ <= pm+M with pm = running min over any seen subset
// (pm >= true min, so argmin and all margin-ties always collected); filter vs final
// min; exact rescore (invariant chain) + lexicographic atomicMin == first-min index.
// EXACT-INVARIANT (verified rel_err==0.0 thirteen times, unchanged in rescore path):
//   d_k = fl32(fl32(S+E_k) - 2*dot_k); dot_k sequential fp32 FMA chain d=0..63
//   S = 4-lane stride-4 sums (l0+l2)+(l1+l3); argmin first-min ascending k
//   out = fl(x + fl(q - x))
__global__ __launch_bounds__(THREADS, 1)
void k_main(const float* __restrict__ in, const float* __restrict__ emb,
            float* __restrict__ out, int write_extras) {
    extern __shared__ float s[];
    float* sE   = s + OFF_E;
    float* sS   = s + OFF_S;
    float* sSA  = s + OFF_SA;
    float* sSl  = s + OFF_SL;
    float* sSlA = s + OFF_SLA;
    float* sX   = s + OFF_X;
    ull*   sLex = (ull*)(s + OFF_LEX);
    int*   sApp = (int*)(s + OFF_APP);
    int*   sBi  = (int*)(s + OFF_BI);
    int*   sGc  = (int*)(s + OFF_GC);
    int*   sOvf = (int*)(s + OFF_OVF);
    int*   sGl  = (int*)(s + OFF_GL);
    int2*  sWl  = (int2*)(s + OFF_WL);
    __nv_bfloat16* sXh = (__nv_bfloat16*)(s + OFF_XH);
    __nv_bfloat16* sEh = (__nv_bfloat16*)(s + OFF_EH);
    __shared__ double red[16];

    const int tid  = threadIdx.x;
    const int lane = tid & 31;
    const int warp = tid >> 5;
    const int vg   = warp >> 1;
    const int ch   = warp & 1;
    const int g    = lane >> 2;
    const int t    = lane & 3;
    const int dg   = tid >> 7;   // staging d-group (d == dg mod 4)
    const int vv   = tid & 127;  // staging vector

    // ---- one-time: bf16 codebook (padded) + exact E_k (XLA 4-lane) ----
#pragma unroll
    for (int i = 0; i < 64; i++) {
        int lin = i * THREADS + tid;
        int code = lin >> 6, d = lin & 63;
        sEh[code * XH_STR + d] = __float2bfloat16_rn(emb[lin]);
    }
    {
        const float* r = emb + tid * D;
        float l0 = 0.f, l1 = 0.f, l2 = 0.f, l3 = 0.f;
#pragma unroll
        for (int i = 0; i < 16; i++) {
            l0 = __fadd_rn(l0, __fmul_rn(r[4 * i + 0], r[4 * i + 0]));
            l1 = __fadd_rn(l1, __fmul_rn(r[4 * i + 1], r[4 * i + 1]));
            l2 = __fadd_rn(l2, __fmul_rn(r[4 * i + 2], r[4 * i + 2]));
            l3 = __fadd_rn(l3, __fmul_rn(r[4 * i + 3], r[4 * i + 3]));
        }
        sE[tid] = __fadd_rn(__fadd_rn(l0, l2), __fadd_rn(l1, l3));
    }
    __syncthreads();

    float lsumf = 0.0f;

    for (int tile = blockIdx.x; tile < NTILE; tile += NCTA) {
        const int v0 = tile * VTILE;
        const int b  = v0 >> 12;
        const int p  = v0 & 4095;
        const float* xg = in + b * (D * HW) + p;

        // ---- init + staging with fused S lane partials ----
        if (tid < VTILE) { sApp[tid] = 0x7F800000; sLex[tid] = ~0ull; }
        if (tid == 0) { *sGc = 0; *sOvf = 0; }
        {
            float lq = 0.f, la = 0.f;
#pragma unroll
            for (int i = 0; i < 16; i++) {
                int lin = i * THREADS + tid;       // d = i*4+dg (ascending), vv fixed
                int d = lin >> 7;
                float x = xg[d * HW + vv];
                sX[lin] = x;
                lq = __fadd_rn(lq, __fmul_rn(x, x));   // exactly XLA lane dg
                la += fabsf(x);
            }
            sSl[dg * 128 + vv] = lq;
            sSlA[dg * 128 + vv] = la;
        }
        __syncthreads();

        // ---- combine S/SA (exact lane combine) + bf16 x tile ----
        if (tid < VTILE) {
            sS[tid]  = __fadd_rn(__fadd_rn(sSl[0 * 128 + tid], sSl[2 * 128 + tid]),
                                 __fadd_rn(sSl[1 * 128 + tid], sSl[3 * 128 + tid]));
            sSA[tid] = (sSlA[0 * 128 + tid] + sSlA[2 * 128 + tid]) +
                       (sSlA[1 * 128 + tid] + sSlA[3 * 128 + tid]);
        }
#pragma unroll
        for (int i = 0; i < 16; i++) {
            int lin = i * THREADS + tid;
            int d = lin >> 7, vx = lin & 127;
            sXh[vx * XH_STR + d] = __float2bfloat16_rn(sX[lin]);
        }
        __syncthreads();

        // ---- A fragments for this warp's 16 rows ----
        const int rowA = vg * 16 + g;
        const int rowB = rowA + 8;
        unsigned afr[4][4];
#pragma unroll
        for (int ks = 0; ks < 4; ks++) {
            int k0 = ks * 16 + t * 2;
            afr[ks][0] = *(const unsigned*)(sXh + rowA * XH_STR + k0);
            afr[ks][1] = *(const unsigned*)(sXh + rowB * XH_STR + k0);
            afr[ks][2] = *(const unsigned*)(sXh + rowA * XH_STR + k0 + 8);
            afr[ks][3] = *(const unsigned*)(sXh + rowB * XH_STR + k0 + 8);
        }
        const float Sa = sS[rowA], Sb = sS[rowB];
        const float MA = sSA[rowA] * 2.0e-5f + 5.0e-5f;
        const float MB = sSA[rowB] * 2.0e-5f + 5.0e-5f;

        // ---- single MMA pass: distances + prefix-min candidate collection ----
        float pmA = 3.4e38f, pmB = 3.4e38f;
        int cnt = 0;
        int2* mywl = sWl + tid * CAPL;

        for (int nt = 0; nt < 32; nt++) {
            const int n0 = ch * 256 + nt * 8;
            const int codeB = n0 + g;
            float cA0 = 0.f, cA1 = 0.f, cA2 = 0.f, cA3 = 0.f;
            float cB0 = 0.f, cB1 = 0.f, cB2 = 0.f, cB3 = 0.f;
#pragma unroll
            for (int ks = 0; ks < 2; ks++) {
                unsigned b0 = *(const unsigned*)(sEh + codeB * XH_STR + ks * 16 + t * 2);
                unsigned b1 = *(const unsigned*)(sEh + codeB * XH_STR + ks * 16 + t * 2 + 8);
                mma16816(cA0, cA1, cA2, cA3, afr[ks][0], afr[ks][1], afr[ks][2], afr[ks][3], b0, b1);
            }
#pragma unroll
            for (int ks = 2; ks < 4; ks++) {
                unsigned b0 = *(const unsigned*)(sEh + codeB * XH_STR + ks * 16 + t * 2);
                unsigned b1 = *(const unsigned*)(sEh + codeB * XH_STR + ks * 16 + t * 2 + 8);
                mma16816(cB0, cB1, cB2, cB3, afr[ks][0], afr[ks][1], afr[ks][2], afr[ks][3], b0, b1);
            }
            const float c0 = cA0 + cB0, c1 = cA1 + cB1, c2 = cA2 + cB2, c3 = cA3 + cB3;

            const int col0 = n0 + t * 2;
            float2 Ep = *(const float2*)(sE + col0);
            float d00 = __fmaf_rn(-2.f, c0, __fadd_rn(Sa, Ep.x));
            float d01 = __fmaf_rn(-2.f, c1, __fadd_rn(Sa, Ep.y));
            float d10 = __fmaf_rn(-2.f, c2, __fadd_rn(Sb, Ep.x));
            float d11 = __fmaf_rn(-2.f, c3, __fadd_rn(Sb, Ep.y));

            // collect vs stale prefix min (superset of final margin set -> sound)
            if (d00 <= pmA + MA) {
                if (cnt < CAPL) mywl[cnt++] = make_int2(__float_as_int(d00), (rowA << 16) | col0);
                else *sOvf = 1;
            }
            if (d01 <= pmA + MA) {
                if (cnt < CAPL) mywl[cnt++] = make_int2(__float_as_int(d01), (rowA << 16) | (col0 + 1));
                else *sOvf = 1;
            }
            if (d10 <= pmB + MB) {
                if (cnt < CAPL) mywl[cnt++] = make_int2(__float_as_int(d10), (rowB << 16) | col0);
                else *sOvf = 1;
            }
            if (d11 <= pmB + MB) {
                if (cnt < CAPL) mywl[cnt++] = make_int2(__float_as_int(d11), (rowB << 16) | (col0 + 1));
                else *sOvf = 1;
            }

            pmA = fminf(pmA, fminf(d00, d01));
            pmB = fminf(pmB, fminf(d10, d11));
            pmA = fminf(pmA, __shfl_xor_sync(0xffffffffu, pmA, 1));
            pmA = fminf(pmA, __shfl_xor_sync(0xffffffffu, pmA, 2));
            pmB = fminf(pmB, __shfl_xor_sync(0xffffffffu, pmB, 1));
            pmB = fminf(pmB, __shfl_xor_sync(0xffffffffu, pmB, 2));
        }
        if (t == 0) {
            atomicMin(sApp + rowA, __float_as_int(pmA));
            atomicMin(sApp + rowB, __float_as_int(pmB));
        }
        __syncthreads();

        // ---- filter own stash vs final threshold -> global candidate list ----
        for (int j = 0; j < cnt; j++) {
            int2 e = mywl[j];
            int rk = e.y;
            int rl = rk >> 16;
            float thr = __int_as_float(sApp[rl]) + (sSA[rl] * 2.0e-5f + 5.0e-5f);
            if (__int_as_float(e.x) <= thr) {
                int slot = atomicAdd(sGc, 1);
                if (slot < GCAP) sGl[slot] = rk;
                else *sOvf = 1;
            }
        }
        __syncthreads();

        // ---- batched EXACT rescore (invariant chain, bit-for-bit) ----
        {
            int gn = *sGc; if (gn > GCAP) gn = GCAP;
            for (int i = tid; i < gn; i += THREADS) {
                int rk = sGl[i];
                int rl = rk >> 16, k = rk & 0xFFFF;
                const float* eg = emb + k * D;
                float dot = 0.f;
#pragma unroll 16
                for (int d = 0; d < 64; d++)
                    dot = __fmaf_rn(sX[d * VTILE + rl], eg[d], dot);
                float t1 = __fadd_rn(sS[rl], sE[k]);
                float de = __fmaf_rn(-2.0f, dot, t1);
                atomicMin(sLex + rl, ((ull)(unsigned)__float_as_int(de) << 32) | (unsigned)k);
            }
            if (*sOvf) {   // never-taken correctness net: rescore everything
                for (int i = tid; i < VTILE * K; i += THREADS) {
                    int rl = i >> 9, k = i & 511;
                    const float* eg = emb + k * D;
                    float dot = 0.f;
#pragma unroll 16
                    for (int d = 0; d < 64; d++)
                        dot = __fmaf_rn(sX[d * VTILE + rl], eg[d], dot);
                    float t1 = __fadd_rn(sS[rl], sE[k]);
                    float de = __fmaf_rn(-2.0f, dot, t1);
                    atomicMin(sLex + rl, ((ull)(unsigned)__float_as_int(de) << 32) | (unsigned)k);
                }
            }
        }
        __syncthreads();

        // ---- indices ----
        if (tid < VTILE) {
            int bi = (int)(sLex[tid] & 0xFFFFFFFFull);
            sBi[tid] = bi;
            if (write_extras) out[IDX_OFF + v0 + tid] = (float)bi;
        }
        __syncthreads();

        // ---- gather exact codes + straight-through store + loss ----
        {
            const int d0 = dg * 16;
            const int bi = sBi[vv];
            const float* eg = emb + bi * D;
            float* og = out + b * (D * HW) + p + vv;
#pragma unroll
            for (int j = 0; j < 16; j++) {
                const int d = d0 + j;
                float q  = eg[d];
                float xs = sX[d * VTILE + vv];
                float tt = __fsub_rn(q, xs);       // fl(q - x)
                og[d * HW] = __fadd_rn(xs, tt);    // fl(x + (q - x))
                lsumf = __fmaf_rn(tt, tt, lsumf);
            }
        }
        __syncthreads();
    }

    // ---- loss block-reduce -> atomic; last CTA finalizes & resets globals ----
#pragma unroll
    for (int o = 16; o; o >>= 1) lsumf += __shfl_down_sync(0xffffffffu, lsumf, o);
    if ((tid & 31) == 0) red[tid >> 5] = (double)lsumf;
    __syncthreads();
    if (tid == 0) {
        double tt = 0.0;
#pragma unroll
        for (int w = 0; w < 16; w++) tt += red[w];
        atomicAdd(&g_loss, tt);
        __threadfence();
        unsigned done = atomicAdd(&g_done, 1u);
        if (done == (unsigned)(gridDim.x - 1)) {
            if (write_extras)
                out[LOSS_OFF] = (float)(0.25 * g_loss / (double)N_ELEMS);
            g_loss = 0.0;
            g_done = 0u;
        }
    }
}

extern "C" void kernel_launch(void* const* d_in, const int* in_sizes, int n_in,
                              void* d_out, int out_size) {
    const float* in  = (const float*)d_in[0];
    const float* emb = (const float*)d_in[1];
    if (n_in >= 2 && in_sizes[0] == K * D && in_sizes[1] == N_ELEMS) {
        const float* t = in; in = emb; emb = t;
    }
    float* out = (float*)d_out;

    cudaFuncSetAttribute(k_main, cudaFuncAttributeMaxDynamicSharedMemorySize, SMEM_BYTES);

    const int extras = (out_size > N_ELEMS) ? 1 : 0;

    k_main<<<NCTA, THREADS, SMEM_BYTES>>>(in, emb, out, extras);
}